// round 3
// baseline (speedup 1.0000x reference)
#include <cuda_runtime.h>
#include <math_constants.h>
#include <cstdint>

// ---------------------------------------------------------------------------
// Problem constants
// ---------------------------------------------------------------------------
#define BATCH     8192
#define IN_DIM    4096
#define LAT       512
#define NCODE     8192
#define PRED_ELEMS ((size_t)BATCH * IN_DIM)      // 33,554,432
#define LOSS_OFF   PRED_ELEMS                    // scalar vq_loss
#define IDX_OFF    (PRED_ELEMS + 1)              // 8192 indices (as float)

// ---------------------------------------------------------------------------
// Scratch (static device globals; no allocation anywhere)
// ---------------------------------------------------------------------------
__device__ float g_bufA[(size_t)BATCH * 4096];   // 128 MB
__device__ float g_bufB[(size_t)BATCH * 2048];   // 64 MB
__device__ float g_bufC[(size_t)BATCH * 1024];   // 32 MB
__device__ float g_bufD[(size_t)BATCH * 512];    // 16 MB  (h3, then z_st)
__device__ float g_bufZ[(size_t)BATCH * 512];    // 16 MB  (z)
__device__ float g_znorm[BATCH];
__device__ float g_enorm[NCODE];
__device__ float g_cand_d[64 * BATCH];
__device__ int   g_cand_i[64 * BATCH];
__device__ int   g_idx[BATCH];
__device__ float g_lossPart[BATCH];

// ---------------------------------------------------------------------------
// SGEMM: C[M,N] = act(A[M,K] @ W[N,K]^T + bias[N])
// 128x128 block tile, BK=16, 8x8 per thread, 256 threads. All dims here are
// multiples of 128 (M) / 128 (N) / 16 (K).
// ---------------------------------------------------------------------------
template <bool RELU>
__global__ __launch_bounds__(256)
void sgemm_bias(const float* __restrict__ A, const float* __restrict__ W,
                const float* __restrict__ bias, float* __restrict__ C,
                int M, int N, int K)
{
    __shared__ float As[16][132];
    __shared__ float Ws[16][132];

    const int tid  = threadIdx.x;
    const int brow = blockIdx.y * 128;
    const int bcol = blockIdx.x * 128;

    const int lr = tid >> 2;          // 0..63
    const int lk = (tid & 3) << 2;    // 0,4,8,12
    const float* Ap = A + (size_t)(brow + lr) * K + lk;
    const float* Wp = W + (size_t)(bcol + lr) * K + lk;

    const int trow = (tid >> 4) << 3; // 0..120
    const int tcol = (tid & 15) << 3;

    float acc[8][8];
#pragma unroll
    for (int i = 0; i < 8; i++)
#pragma unroll
        for (int j = 0; j < 8; j++) acc[i][j] = 0.0f;

    for (int k0 = 0; k0 < K; k0 += 16) {
#pragma unroll
        for (int h = 0; h < 2; h++) {
            float4 a = *(const float4*)(Ap + (size_t)(h * 64) * K + k0);
            float4 w = *(const float4*)(Wp + (size_t)(h * 64) * K + k0);
            int r = lr + h * 64;
            As[lk + 0][r] = a.x; As[lk + 1][r] = a.y;
            As[lk + 2][r] = a.z; As[lk + 3][r] = a.w;
            Ws[lk + 0][r] = w.x; Ws[lk + 1][r] = w.y;
            Ws[lk + 2][r] = w.z; Ws[lk + 3][r] = w.w;
        }
        __syncthreads();
#pragma unroll
        for (int kk = 0; kk < 16; kk++) {
            float ra[8], rb[8];
            *(float4*)(ra)     = *(const float4*)&As[kk][trow];
            *(float4*)(ra + 4) = *(const float4*)&As[kk][trow + 4];
            *(float4*)(rb)     = *(const float4*)&Ws[kk][tcol];
            *(float4*)(rb + 4) = *(const float4*)&Ws[kk][tcol + 4];
#pragma unroll
            for (int i = 0; i < 8; i++)
#pragma unroll
                for (int j = 0; j < 8; j++)
                    acc[i][j] = fmaf(ra[i], rb[j], acc[i][j]);
        }
        __syncthreads();
    }

#pragma unroll
    for (int i = 0; i < 8; i++) {
        int row = brow + trow + i;
#pragma unroll
        for (int j = 0; j < 8; j += 4) {
            int col = bcol + tcol + j;
            float4 bv = *(const float4*)&bias[col];
            float4 v;
            v.x = acc[i][j + 0] + bv.x;
            v.y = acc[i][j + 1] + bv.y;
            v.z = acc[i][j + 2] + bv.z;
            v.w = acc[i][j + 3] + bv.w;
            if (RELU) {
                v.x = fmaxf(v.x, 0.0f); v.y = fmaxf(v.y, 0.0f);
                v.z = fmaxf(v.z, 0.0f); v.w = fmaxf(v.w, 0.0f);
            }
            *(float4*)&C[(size_t)row * N + col] = v;
        }
    }
}

// ---------------------------------------------------------------------------
// Row squared-norm: out[row] = sum_k X[row,k]^2   (D = 512, one warp per row)
// ---------------------------------------------------------------------------
__global__ void rownorm512(const float* __restrict__ X, float* __restrict__ out,
                           int rows)
{
    int warp = (blockIdx.x * blockDim.x + threadIdx.x) >> 5;
    int lane = threadIdx.x & 31;
    if (warp >= rows) return;
    const float* xp = X + (size_t)warp * 512;
    float s = 0.0f;
#pragma unroll
    for (int k = lane; k < 512; k += 32) { float v = xp[k]; s = fmaf(v, v, s); }
#pragma unroll
    for (int o = 16; o; o >>= 1) s += __shfl_xor_sync(0xffffffffu, s, o);
    if (lane == 0) out[warp] = s;
}

// ---------------------------------------------------------------------------
// VQ stage A: per (128-row, 128-code) tile, compute the reference distance
//   d = fl( fl(znorm + enorm) - 2*dot )
// and reduce to per-(row, code-block) argmin with smallest-index tie-break.
// M = N = 8192, K = 512.
// ---------------------------------------------------------------------------
__global__ __launch_bounds__(256)
void vq_dist(const float* __restrict__ Z, const float* __restrict__ CB,
             const float* __restrict__ zn, const float* __restrict__ en,
             float* __restrict__ cand_d, int* __restrict__ cand_i)
{
    __shared__ float As[16][132];
    __shared__ float Ws[16][132];
    __shared__ float sd[128][17];
    __shared__ int   si[128][16];

    const int K = 512;
    const int tid  = threadIdx.x;
    const int brow = blockIdx.y * 128;
    const int bcol = blockIdx.x * 128;

    const int lr = tid >> 2;
    const int lk = (tid & 3) << 2;
    const float* Ap = Z  + (size_t)(brow + lr) * K + lk;
    const float* Wp = CB + (size_t)(bcol + lr) * K + lk;

    const int trow = (tid >> 4) << 3;
    const int tcol = (tid & 15) << 3;

    float acc[8][8];
#pragma unroll
    for (int i = 0; i < 8; i++)
#pragma unroll
        for (int j = 0; j < 8; j++) acc[i][j] = 0.0f;

    for (int k0 = 0; k0 < K; k0 += 16) {
#pragma unroll
        for (int h = 0; h < 2; h++) {
            float4 a = *(const float4*)(Ap + (size_t)(h * 64) * K + k0);
            float4 w = *(const float4*)(Wp + (size_t)(h * 64) * K + k0);
            int r = lr + h * 64;
            As[lk + 0][r] = a.x; As[lk + 1][r] = a.y;
            As[lk + 2][r] = a.z; As[lk + 3][r] = a.w;
            Ws[lk + 0][r] = w.x; Ws[lk + 1][r] = w.y;
            Ws[lk + 2][r] = w.z; Ws[lk + 3][r] = w.w;
        }
        __syncthreads();
#pragma unroll
        for (int kk = 0; kk < 16; kk++) {
            float ra[8], rb[8];
            *(float4*)(ra)     = *(const float4*)&As[kk][trow];
            *(float4*)(ra + 4) = *(const float4*)&As[kk][trow + 4];
            *(float4*)(rb)     = *(const float4*)&Ws[kk][tcol];
            *(float4*)(rb + 4) = *(const float4*)&Ws[kk][tcol + 4];
#pragma unroll
            for (int i = 0; i < 8; i++)
#pragma unroll
                for (int j = 0; j < 8; j++)
                    acc[i][j] = fmaf(ra[i], rb[j], acc[i][j]);
        }
        __syncthreads();
    }

    const int tx = tid & 15;
#pragma unroll
    for (int i = 0; i < 8; i++) {
        int row = trow + i;
        float znv = zn[brow + row];
        float best = CUDART_INF_F;
        int   bi   = 0;
#pragma unroll
        for (int j = 0; j < 8; j++) {          // ascending code index
            int code = bcol + tcol + j;
            float t = znv + en[code];          // fl(znorm + enorm)
            float d = t - 2.0f * acc[i][j];    // fl(t - 2*dot)  (2*dot exact)
            if (d < best) { best = d; bi = code; }
        }
        sd[row][tx] = best;
        si[row][tx] = bi;
    }
    __syncthreads();

    if (tid < 128) {
        float best = sd[tid][0];
        int   bi   = si[tid][0];
#pragma unroll
        for (int c = 1; c < 16; c++) {         // ascending code groups
            float d = sd[tid][c];
            if (d < best) { best = d; bi = si[tid][c]; }
        }
        cand_d[(size_t)blockIdx.x * BATCH + brow + tid] = best;
        cand_i[(size_t)blockIdx.x * BATCH + brow + tid] = bi;
    }
}

// ---------------------------------------------------------------------------
// VQ stage B: final argmin over 64 code-block candidates per row.
// Writes int index + float index into the output buffer.
// ---------------------------------------------------------------------------
__global__ void vq_argmin_final(const float* __restrict__ cand_d,
                                const int* __restrict__ cand_i,
                                int* __restrict__ idx,
                                float* __restrict__ out_idx)
{
    int row = blockIdx.x * blockDim.x + threadIdx.x;
    if (row >= BATCH) return;
    float best = cand_d[row];
    int   bi   = cand_i[row];
#pragma unroll
    for (int c = 1; c < 64; c++) {             // ascending code blocks
        float d = cand_d[(size_t)c * BATCH + row];
        if (d < best) { best = d; bi = cand_i[(size_t)c * BATCH + row]; }
    }
    idx[row] = bi;
    out_idx[row] = (float)bi;
}

// ---------------------------------------------------------------------------
// Gather z_q, compute z_st = z + (z_q - z) with reference rounding, and the
// per-row partial of sum((z_q - z)^2). One block (128 thr) per row.
// ---------------------------------------------------------------------------
__global__ __launch_bounds__(128)
void vq_gather(const float* __restrict__ Z, const float* __restrict__ CB,
               const int* __restrict__ idx, float* __restrict__ zst,
               float* __restrict__ lossPart)
{
    __shared__ float sh[128];
    int row = blockIdx.x;
    int tid = threadIdx.x;
    int code = idx[row];

    const float4 zv = ((const float4*)(Z  + (size_t)row  * 512))[tid];
    const float4 ev = ((const float4*)(CB + (size_t)code * 512))[tid];
    float4 st;
    float d0 = ev.x - zv.x; st.x = zv.x + d0;
    float d1 = ev.y - zv.y; st.y = zv.y + d1;
    float d2 = ev.z - zv.z; st.z = zv.z + d2;
    float d3 = ev.w - zv.w; st.w = zv.w + d3;
    ((float4*)(zst + (size_t)row * 512))[tid] = st;

    float s = d0 * d0 + d1 * d1 + d2 * d2 + d3 * d3;
    sh[tid] = s;
    __syncthreads();
#pragma unroll
    for (int o = 64; o; o >>= 1) {
        if (tid < o) sh[tid] += sh[tid + o];
        __syncthreads();
    }
    if (tid == 0) lossPart[row] = sh[0];
}

__global__ void loss_final(const float* __restrict__ part, float* __restrict__ out)
{
    __shared__ float sh[256];
    int tid = threadIdx.x;
    float s = 0.0f;
    for (int i = tid; i < BATCH; i += 256) s += part[i];   // fixed order
    sh[tid] = s;
    __syncthreads();
#pragma unroll
    for (int o = 128; o; o >>= 1) {
        if (tid < o) sh[tid] += sh[tid + o];
        __syncthreads();
    }
    if (tid == 0)
        *out = 1.25f * (sh[0] / (float)(BATCH * 512));
}

// ---------------------------------------------------------------------------
// Launch
// ---------------------------------------------------------------------------
static float *p_bufA, *p_bufB, *p_bufC, *p_bufD, *p_bufZ;
static float *p_znorm, *p_enorm, *p_cand_d, *p_lossPart;
static int   *p_cand_i, *p_idx;
static bool   s_init = false;

extern "C" void kernel_launch(void* const* d_in, const int* in_sizes, int n_in,
                              void* d_out, int out_size)
{
    if (!s_init) {
        cudaGetSymbolAddress((void**)&p_bufA, g_bufA);
        cudaGetSymbolAddress((void**)&p_bufB, g_bufB);
        cudaGetSymbolAddress((void**)&p_bufC, g_bufC);
        cudaGetSymbolAddress((void**)&p_bufD, g_bufD);
        cudaGetSymbolAddress((void**)&p_bufZ, g_bufZ);
        cudaGetSymbolAddress((void**)&p_znorm, g_znorm);
        cudaGetSymbolAddress((void**)&p_enorm, g_enorm);
        cudaGetSymbolAddress((void**)&p_cand_d, g_cand_d);
        cudaGetSymbolAddress((void**)&p_cand_i, g_cand_i);
        cudaGetSymbolAddress((void**)&p_idx, g_idx);
        cudaGetSymbolAddress((void**)&p_lossPart, g_lossPart);
        s_init = true;
    }

    const float* x   = (const float*)d_in[0];
    const float* ew1 = (const float*)d_in[1];
    const float* eb1 = (const float*)d_in[2];
    const float* ew2 = (const float*)d_in[3];
    const float* eb2 = (const float*)d_in[4];
    const float* ew3 = (const float*)d_in[5];
    const float* eb3 = (const float*)d_in[6];
    const float* ew4 = (const float*)d_in[7];
    const float* eb4 = (const float*)d_in[8];
    const float* cb  = (const float*)d_in[9];
    const float* dw1 = (const float*)d_in[10];
    const float* db1 = (const float*)d_in[11];
    const float* dw2 = (const float*)d_in[12];
    const float* db2 = (const float*)d_in[13];
    const float* dw3 = (const float*)d_in[14];
    const float* db3 = (const float*)d_in[15];
    const float* dw4 = (const float*)d_in[16];
    const float* db4 = (const float*)d_in[17];
    float* out = (float*)d_out;

    dim3 blk(256);

    // ---- encoder ----
    sgemm_bias<true ><<<dim3(2048/128, BATCH/128), blk>>>(x,      ew1, eb1, p_bufB, BATCH, 2048, 4096);
    sgemm_bias<true ><<<dim3(1024/128, BATCH/128), blk>>>(p_bufB, ew2, eb2, p_bufC, BATCH, 1024, 2048);
    sgemm_bias<true ><<<dim3( 512/128, BATCH/128), blk>>>(p_bufC, ew3, eb3, p_bufD, BATCH,  512, 1024);
    sgemm_bias<false><<<dim3( 512/128, BATCH/128), blk>>>(p_bufD, ew4, eb4, p_bufZ, BATCH,  512,  512);

    // ---- VQ ----
    rownorm512<<<(BATCH * 32 + 255) / 256, blk>>>(p_bufZ, p_znorm, BATCH);
    rownorm512<<<(NCODE * 32 + 255) / 256, blk>>>(cb,     p_enorm, NCODE);
    vq_dist<<<dim3(NCODE/128, BATCH/128), blk>>>(p_bufZ, cb, p_znorm, p_enorm,
                                                 p_cand_d, p_cand_i);
    vq_argmin_final<<<BATCH/256, blk>>>(p_cand_d, p_cand_i, p_idx, out + IDX_OFF);
    vq_gather<<<BATCH, 128>>>(p_bufZ, cb, p_idx, p_bufD, p_lossPart);
    loss_final<<<1, 256>>>(p_lossPart, out + LOSS_OFF);

    // ---- decoder ----
    sgemm_bias<true ><<<dim3(1024/128, BATCH/128), blk>>>(p_bufD, dw1, db1, p_bufC, BATCH, 1024,  512);
    sgemm_bias<true ><<<dim3(2048/128, BATCH/128), blk>>>(p_bufC, dw2, db2, p_bufB, BATCH, 2048, 1024);
    sgemm_bias<true ><<<dim3(4096/128, BATCH/128), blk>>>(p_bufB, dw3, db3, p_bufA, BATCH, 4096, 2048);
    sgemm_bias<false><<<dim3(4096/128, BATCH/128), blk>>>(p_bufA, dw4, db4, out,    BATCH, 4096, 4096);
}

// round 12
// speedup vs baseline: 1.5265x; 1.5265x over previous
#include <cuda_runtime.h>
#include <cuda_fp16.h>
#include <math_constants.h>
#include <cstdint>

// ---------------------------------------------------------------------------
// Problem constants
// ---------------------------------------------------------------------------
#define BATCH     8192
#define NCODE     8192
#define PRED_ELEMS ((size_t)BATCH * 4096)
#define LOSS_OFF   PRED_ELEMS
#define IDX_OFF    (PRED_ELEMS + 1)

// Exact power-of-2 scales keeping fp16 'lo' residuals in normal range
#define WSCALE 1024.0f
#define ASCALE 32.0f
#define UNSCALE (1.0f / (WSCALE * ASCALE))

// ---------------------------------------------------------------------------
// Helpers
// ---------------------------------------------------------------------------
__device__ __forceinline__ uint32_t smem_u32(const void* p) {
    uint32_t a;
    asm("{ .reg .u64 t; cvta.to.shared.u64 t, %1; cvt.u32.u64 %0, t; }"
        : "=r"(a) : "l"(p));
    return a;
}
__device__ __forceinline__ void cp_async16(uint32_t dst, const void* src) {
    asm volatile("cp.async.cg.shared.global [%0], [%1], 16;" :: "r"(dst), "l"(src) : "memory");
}
#define CP_COMMIT() asm volatile("cp.async.commit_group;" ::: "memory")
#define CP_WAIT2()  asm volatile("cp.async.wait_group 2;" ::: "memory")

__device__ __forceinline__ void ldsm4(uint32_t* r, uint32_t addr) {
    asm volatile("ldmatrix.sync.aligned.m8n8.x4.shared.b16 {%0,%1,%2,%3}, [%4];"
                 : "=r"(r[0]), "=r"(r[1]), "=r"(r[2]), "=r"(r[3]) : "r"(addr));
}
__device__ __forceinline__ void mma16816(float* c, const uint32_t* a, const uint32_t* b) {
    asm volatile("mma.sync.aligned.m16n8k16.row.col.f32.f16.f16.f32 "
                 "{%0,%1,%2,%3}, {%4,%5,%6,%7}, {%8,%9}, {%0,%1,%2,%3};"
                 : "+f"(c[0]), "+f"(c[1]), "+f"(c[2]), "+f"(c[3])
                 : "r"(a[0]), "r"(a[1]), "r"(a[2]), "r"(a[3]), "r"(b[0]), "r"(b[1]));
}

// ---------------------------------------------------------------------------
// Scratch buffers
// ---------------------------------------------------------------------------
// fp32 encoder activations (R3-identical path)
__device__ float g_bufB[(size_t)BATCH * 2048];   // 64 MB
__device__ float g_bufC[(size_t)BATCH * 1024];   // 32 MB
__device__ float g_bufD[(size_t)BATCH * 512];    // 16 MB
__device__ float g_bufZ[(size_t)BATCH * 512];    // 16 MB
// fp16 hi/lo pairs for the HMMA decoder
__device__ __half g_zsth[4194304], g_zstl[4194304];
__device__ __half g_g1h[8388608],  g_g1l[8388608];
__device__ __half g_g2h[16777216], g_g2l[16777216];
__device__ __half g_g3h[33554432], g_g3l[33554432];
__device__ __half g_v1h[524288],   g_v1l[524288];
__device__ __half g_v2h[2097152],  g_v2l[2097152];
__device__ __half g_v3h[8388608],  g_v3l[8388608];
__device__ __half g_v4h[16777216], g_v4l[16777216];
// VQ scratch
__device__ float g_znorm[BATCH];
__device__ float g_enorm[NCODE];
__device__ float g_cand_d[64 * BATCH];
__device__ int   g_cand_i[64 * BATCH];
__device__ int   g_idx[BATCH];
__device__ float g_lossPart[BATCH];

// ---------------------------------------------------------------------------
// fp32 SGEMM (R3-identical): C[M,N] = act(A[M,K] @ W[N,K]^T + bias[N])
// 128x128 block tile, BK=16, 8x8 per thread, 256 threads.
// ---------------------------------------------------------------------------
template <bool RELU>
__global__ __launch_bounds__(256)
void sgemm_bias(const float* __restrict__ A, const float* __restrict__ W,
                const float* __restrict__ bias, float* __restrict__ C,
                int M, int N, int K)
{
    __shared__ float As[16][132];
    __shared__ float Ws[16][132];

    const int tid  = threadIdx.x;
    const int brow = blockIdx.y * 128;
    const int bcol = blockIdx.x * 128;

    const int lr = tid >> 2;          // 0..63
    const int lk = (tid & 3) << 2;    // 0,4,8,12
    const float* Ap = A + (size_t)(brow + lr) * K + lk;
    const float* Wp = W + (size_t)(bcol + lr) * K + lk;

    const int trow = (tid >> 4) << 3; // 0..120
    const int tcol = (tid & 15) << 3;

    float acc[8][8];
#pragma unroll
    for (int i = 0; i < 8; i++)
#pragma unroll
        for (int j = 0; j < 8; j++) acc[i][j] = 0.0f;

    for (int k0 = 0; k0 < K; k0 += 16) {
#pragma unroll
        for (int h = 0; h < 2; h++) {
            float4 a = *(const float4*)(Ap + (size_t)(h * 64) * K + k0);
            float4 w = *(const float4*)(Wp + (size_t)(h * 64) * K + k0);
            int r = lr + h * 64;
            As[lk + 0][r] = a.x; As[lk + 1][r] = a.y;
            As[lk + 2][r] = a.z; As[lk + 3][r] = a.w;
            Ws[lk + 0][r] = w.x; Ws[lk + 1][r] = w.y;
            Ws[lk + 2][r] = w.z; Ws[lk + 3][r] = w.w;
        }
        __syncthreads();
#pragma unroll
        for (int kk = 0; kk < 16; kk++) {
            float ra[8], rb[8];
            *(float4*)(ra)     = *(const float4*)&As[kk][trow];
            *(float4*)(ra + 4) = *(const float4*)&As[kk][trow + 4];
            *(float4*)(rb)     = *(const float4*)&Ws[kk][tcol];
            *(float4*)(rb + 4) = *(const float4*)&Ws[kk][tcol + 4];
#pragma unroll
            for (int i = 0; i < 8; i++)
#pragma unroll
                for (int j = 0; j < 8; j++)
                    acc[i][j] = fmaf(ra[i], rb[j], acc[i][j]);
        }
        __syncthreads();
    }

#pragma unroll
    for (int i = 0; i < 8; i++) {
        int row = brow + trow + i;
#pragma unroll
        for (int j = 0; j < 8; j += 4) {
            int col = bcol + tcol + j;
            float4 bv = *(const float4*)&bias[col];
            float4 v;
            v.x = acc[i][j + 0] + bv.x;
            v.y = acc[i][j + 1] + bv.y;
            v.z = acc[i][j + 2] + bv.z;
            v.w = acc[i][j + 3] + bv.w;
            if (RELU) {
                v.x = fmaxf(v.x, 0.0f); v.y = fmaxf(v.y, 0.0f);
                v.z = fmaxf(v.z, 0.0f); v.w = fmaxf(v.w, 0.0f);
            }
            *(float4*)&C[(size_t)row * N + col] = v;
        }
    }
}

// ---------------------------------------------------------------------------
// fp32 -> (fp16 hi, fp16 lo) split of (x * scale)   [scale = exact power of 2]
// ---------------------------------------------------------------------------
__global__ void split4(const float4* __restrict__ src, __half2* __restrict__ h,
                       __half2* __restrict__ l, int n4, float scale)
{
    int i = blockIdx.x * blockDim.x + threadIdx.x;
    if (i >= n4) return;
    float4 x = src[i];
    x.x *= scale; x.y *= scale; x.z *= scale; x.w *= scale;
    __half2 h0 = __floats2half2_rn(x.x, x.y);
    __half2 h1 = __floats2half2_rn(x.z, x.w);
    __half2 l0 = __floats2half2_rn(x.x - __low2float(h0), x.y - __high2float(h0));
    __half2 l1 = __floats2half2_rn(x.z - __low2float(h1), x.w - __high2float(h1));
    h[2 * i] = h0; h[2 * i + 1] = h1;
    l[2 * i] = l0; l[2 * i + 1] = l1;
}

// ---------------------------------------------------------------------------
// HMMA split-fp16 GEMM: C[M,N] = act(UNSCALE * (As[M,K] @ Ws[N,K]^T) + bias)
// 3 products (hi*hi + hi*lo + lo*hi) into one fp32 acc. CTA 128x128,
// 256 threads, warp tile 32x64, K-chunk 32, 3-stage cp.async.
// ---------------------------------------------------------------------------
#define TM 128
#define TN 128
#define KC 32
#define ROWPAD 40
#define PLANE (TM * ROWPAD)              // 5120 halfs per plane
#define STAGE_HALFS (4 * PLANE)          // Ahi,Alo,Whi,Wlo = 20480 halfs
#define GEMM_SMEM (3 * STAGE_HALFS * 2)  // 122880 bytes

template <int RELU, int WS, int WF>
__global__ void __launch_bounds__(256)
tc_gemm(const __half* __restrict__ Ah, const __half* __restrict__ Al,
        const __half* __restrict__ Wh, const __half* __restrict__ Wl,
        const float* __restrict__ bias,
        __half* __restrict__ Ch, __half* __restrict__ Cl,
        float* __restrict__ Cf, int M, int N, int K)
{
    extern __shared__ __half sm[];
    const int tid = threadIdx.x, wid = tid >> 5, lid = tid & 31;
    const int brow = blockIdx.y * TM, bcol = blockIdx.x * TN;
    const int m0 = (wid & 3) * 32;      // warp m-offset
    const int n0 = (wid >> 2) * 64;     // warp n-offset
    const uint32_t sbase = smem_u32(sm);

    auto load_stage = [&](int chunk, int slot) {
        const int kc = chunk * KC;
#pragma unroll
        for (int p = 0; p < 8; p++) {
            int idx = p * 256 + tid;
            int plane = idx >> 9, c = idx & 511, row = c >> 2, seg = c & 3;
            const __half* gsrc;
            if (plane == 0)      gsrc = Ah + (size_t)(brow + row) * K + kc + seg * 8;
            else if (plane == 1) gsrc = Al + (size_t)(brow + row) * K + kc + seg * 8;
            else if (plane == 2) gsrc = Wh + (size_t)(bcol + row) * K + kc + seg * 8;
            else                 gsrc = Wl + (size_t)(bcol + row) * K + kc + seg * 8;
            uint32_t dst = sbase +
                2u * (uint32_t)(slot * STAGE_HALFS + plane * PLANE + row * ROWPAD + seg * 8);
            cp_async16(dst, gsrc);
        }
    };

    float acc[2][8][4];
#pragma unroll
    for (int mt = 0; mt < 2; mt++)
#pragma unroll
        for (int nt = 0; nt < 8; nt++)
#pragma unroll
            for (int q = 0; q < 4; q++) acc[mt][nt][q] = 0.0f;

    const int nch = K / KC;
    load_stage(0, 0); CP_COMMIT();
    load_stage(1, 1); CP_COMMIT();
    load_stage(2, 2); CP_COMMIT();

    for (int i = 0; i < nch; i++) {
        const int slot = i % 3;
        CP_WAIT2();
        __syncthreads();
        const uint32_t aHi = sbase + 2u * (uint32_t)(slot * STAGE_HALFS);
        const uint32_t aLo = aHi + 2u * PLANE;
        const uint32_t bHi = aHi + 4u * PLANE;
        const uint32_t bLo = aHi + 6u * PLANE;

#pragma unroll
        for (int s = 0; s < 2; s++) {
            const int k0 = s * 16;
            uint32_t ah[2][4], al[2][4], bh[8][2], bl[8][2];
#pragma unroll
            for (int mt = 0; mt < 2; mt++) {
                uint32_t off = 2u * (uint32_t)((m0 + mt * 16 + (lid & 15)) * ROWPAD
                                               + k0 + ((lid >> 4) << 3));
                ldsm4(ah[mt], aHi + off);
                ldsm4(al[mt], aLo + off);
            }
#pragma unroll
            for (int g = 0; g < 4; g++) {
                uint32_t off = 2u * (uint32_t)((n0 + g * 16 + (lid & 15)) * ROWPAD
                                               + k0 + ((lid >> 4) << 3));
                uint32_t r[4];
                ldsm4(r, bHi + off);
                bh[g * 2][0] = r[0]; bh[g * 2][1] = r[2];
                bh[g * 2 + 1][0] = r[1]; bh[g * 2 + 1][1] = r[3];
                ldsm4(r, bLo + off);
                bl[g * 2][0] = r[0]; bl[g * 2][1] = r[2];
                bl[g * 2 + 1][0] = r[1]; bl[g * 2 + 1][1] = r[3];
            }
#pragma unroll
            for (int mt = 0; mt < 2; mt++)
#pragma unroll
                for (int nt = 0; nt < 8; nt++) {
                    mma16816(acc[mt][nt], ah[mt], bh[nt]);
                    mma16816(acc[mt][nt], ah[mt], bl[nt]);
                    mma16816(acc[mt][nt], al[mt], bh[nt]);
                }
        }
        __syncthreads();
        if (i + 3 < nch) load_stage(i + 3, slot);
        CP_COMMIT();
    }

    // Epilogue: unscale + bias + ReLU + (fp32 store | fused scaled fp16 split)
#pragma unroll
    for (int mt = 0; mt < 2; mt++) {
#pragma unroll
        for (int nt = 0; nt < 8; nt++) {
            const int col = bcol + n0 + nt * 8 + 2 * (lid & 3);
            const float b0 = bias[col], b1 = bias[col + 1];
#pragma unroll
            for (int h = 0; h < 2; h++) {
                const int row = brow + m0 + mt * 16 + (lid >> 2) + h * 8;
                float v0 = fmaf(acc[mt][nt][h * 2 + 0], UNSCALE, b0);
                float v1 = fmaf(acc[mt][nt][h * 2 + 1], UNSCALE, b1);
                if (RELU) { v0 = fmaxf(v0, 0.0f); v1 = fmaxf(v1, 0.0f); }
                const size_t off = (size_t)row * N + col;
                if (WF) {
                    *(float2*)&Cf[off] = make_float2(v0, v1);
                }
                if (WS) {
                    float s0 = v0 * ASCALE, s1 = v1 * ASCALE;
                    __half2 hh = __floats2half2_rn(s0, s1);
                    __half2 ll = __floats2half2_rn(s0 - __low2float(hh),
                                                   s1 - __high2float(hh));
                    *(__half2*)&Ch[off] = hh;
                    *(__half2*)&Cl[off] = ll;
                }
            }
        }
    }
}

// ---------------------------------------------------------------------------
// VQ path (fp32 — R3-identical, empirically index-exact)
// ---------------------------------------------------------------------------
__global__ void rownorm512(const float* __restrict__ X, float* __restrict__ out, int rows)
{
    int warp = (blockIdx.x * blockDim.x + threadIdx.x) >> 5;
    int lane = threadIdx.x & 31;
    if (warp >= rows) return;
    const float* xp = X + (size_t)warp * 512;
    float s = 0.0f;
#pragma unroll
    for (int k = lane; k < 512; k += 32) { float v = xp[k]; s = fmaf(v, v, s); }
#pragma unroll
    for (int o = 16; o; o >>= 1) s += __shfl_xor_sync(0xffffffffu, s, o);
    if (lane == 0) out[warp] = s;
}

__global__ __launch_bounds__(256)
void vq_dist(const float* __restrict__ Z, const float* __restrict__ CB,
             const float* __restrict__ zn, const float* __restrict__ en,
             float* __restrict__ cand_d, int* __restrict__ cand_i)
{
    __shared__ float As[16][132];
    __shared__ float Ws[16][132];
    __shared__ float sd[128][17];
    __shared__ int   si[128][16];

    const int K = 512;
    const int tid  = threadIdx.x;
    const int brow = blockIdx.y * 128;
    const int bcol = blockIdx.x * 128;

    const int lr = tid >> 2;
    const int lk = (tid & 3) << 2;
    const float* Ap = Z  + (size_t)(brow + lr) * K + lk;
    const float* Wp = CB + (size_t)(bcol + lr) * K + lk;

    const int trow = (tid >> 4) << 3;
    const int tcol = (tid & 15) << 3;

    float acc[8][8];
#pragma unroll
    for (int i = 0; i < 8; i++)
#pragma unroll
        for (int j = 0; j < 8; j++) acc[i][j] = 0.0f;

    for (int k0 = 0; k0 < 512; k0 += 16) {
#pragma unroll
        for (int h = 0; h < 2; h++) {
            float4 a = *(const float4*)(Ap + (size_t)(h * 64) * K + k0);
            float4 w = *(const float4*)(Wp + (size_t)(h * 64) * K + k0);
            int r = lr + h * 64;
            As[lk + 0][r] = a.x; As[lk + 1][r] = a.y;
            As[lk + 2][r] = a.z; As[lk + 3][r] = a.w;
            Ws[lk + 0][r] = w.x; Ws[lk + 1][r] = w.y;
            Ws[lk + 2][r] = w.z; Ws[lk + 3][r] = w.w;
        }
        __syncthreads();
#pragma unroll
        for (int kk = 0; kk < 16; kk++) {
            float ra[8], rb[8];
            *(float4*)(ra)     = *(const float4*)&As[kk][trow];
            *(float4*)(ra + 4) = *(const float4*)&As[kk][trow + 4];
            *(float4*)(rb)     = *(const float4*)&Ws[kk][tcol];
            *(float4*)(rb + 4) = *(const float4*)&Ws[kk][tcol + 4];
#pragma unroll
            for (int i = 0; i < 8; i++)
#pragma unroll
                for (int j = 0; j < 8; j++)
                    acc[i][j] = fmaf(ra[i], rb[j], acc[i][j]);
        }
        __syncthreads();
    }

    const int tx = tid & 15;
#pragma unroll
    for (int i = 0; i < 8; i++) {
        int row = trow + i;
        float znv = zn[brow + row];
        float best = CUDART_INF_F;
        int   bi   = 0;
#pragma unroll
        for (int j = 0; j < 8; j++) {
            int code = bcol + tcol + j;
            float t = znv + en[code];
            float d = t - 2.0f * acc[i][j];
            if (d < best) { best = d; bi = code; }
        }
        sd[row][tx] = best;
        si[row][tx] = bi;
    }
    __syncthreads();

    if (tid < 128) {
        float best = sd[tid][0];
        int   bi   = si[tid][0];
#pragma unroll
        for (int c = 1; c < 16; c++) {
            float d = sd[tid][c];
            if (d < best) { best = d; bi = si[tid][c]; }
        }
        cand_d[(size_t)blockIdx.x * BATCH + brow + tid] = best;
        cand_i[(size_t)blockIdx.x * BATCH + brow + tid] = bi;
    }
}

__global__ void vq_argmin_final(const float* __restrict__ cand_d,
                                const int* __restrict__ cand_i,
                                int* __restrict__ idx,
                                float* __restrict__ out_idx)
{
    int row = blockIdx.x * blockDim.x + threadIdx.x;
    if (row >= BATCH) return;
    float best = cand_d[row];
    int   bi   = cand_i[row];
#pragma unroll
    for (int c = 1; c < 64; c++) {
        float d = cand_d[(size_t)c * BATCH + row];
        if (d < best) { best = d; bi = cand_i[(size_t)c * BATCH + row]; }
    }
    idx[row] = bi;
    out_idx[row] = (float)bi;
}

// z_st = z + (z_q - z); emit scaled fp16 hi/lo split of z_st + loss partials.
__global__ __launch_bounds__(128)
void vq_gather(const float* __restrict__ Z, const float* __restrict__ CB,
               const int* __restrict__ idx,
               __half* __restrict__ zsth, __half* __restrict__ zstl,
               float* __restrict__ lossPart)
{
    __shared__ float sh[128];
    int row = blockIdx.x;
    int tid = threadIdx.x;
    int code = idx[row];

    const float4 zv = ((const float4*)(Z  + (size_t)row  * 512))[tid];
    const float4 ev = ((const float4*)(CB + (size_t)code * 512))[tid];
    float4 st;
    float d0 = ev.x - zv.x; st.x = (zv.x + d0) * ASCALE;
    float d1 = ev.y - zv.y; st.y = (zv.y + d1) * ASCALE;
    float d2 = ev.z - zv.z; st.z = (zv.z + d2) * ASCALE;
    float d3 = ev.w - zv.w; st.w = (zv.w + d3) * ASCALE;

    __half2 h0 = __floats2half2_rn(st.x, st.y);
    __half2 h1 = __floats2half2_rn(st.z, st.w);
    __half2 l0 = __floats2half2_rn(st.x - __low2float(h0), st.y - __high2float(h0));
    __half2 l1 = __floats2half2_rn(st.z - __low2float(h1), st.w - __high2float(h1));
    ((__half2*)(zsth + (size_t)row * 512))[2 * tid]     = h0;
    ((__half2*)(zsth + (size_t)row * 512))[2 * tid + 1] = h1;
    ((__half2*)(zstl + (size_t)row * 512))[2 * tid]     = l0;
    ((__half2*)(zstl + (size_t)row * 512))[2 * tid + 1] = l1;

    float s = d0 * d0 + d1 * d1 + d2 * d2 + d3 * d3;
    sh[tid] = s;
    __syncthreads();
#pragma unroll
    for (int o = 64; o; o >>= 1) {
        if (tid < o) sh[tid] += sh[tid + o];
        __syncthreads();
    }
    if (tid == 0) lossPart[row] = sh[0];
}

__global__ void loss_final(const float* __restrict__ part, float* __restrict__ out)
{
    __shared__ float sh[256];
    int tid = threadIdx.x;
    float s = 0.0f;
    for (int i = tid; i < BATCH; i += 256) s += part[i];
    sh[tid] = s;
    __syncthreads();
#pragma unroll
    for (int o = 128; o; o >>= 1) {
        if (tid < o) sh[tid] += sh[tid + o];
        __syncthreads();
    }
    if (tid == 0) *out = 1.25f * (sh[0] / (float)(BATCH * 512));
}

// ---------------------------------------------------------------------------
// Launch
// ---------------------------------------------------------------------------
#define GETSYM(p, s) cudaGetSymbolAddress((void**)&(p), s)

static float *p_bufB, *p_bufC, *p_bufD, *p_bufZ;
static __half *p_zsth, *p_zstl, *p_g1h, *p_g1l, *p_g2h, *p_g2l, *p_g3h, *p_g3l;
static __half *p_v1h, *p_v1l, *p_v2h, *p_v2l, *p_v3h, *p_v3l, *p_v4h, *p_v4l;
static float *p_znorm, *p_enorm, *p_cand_d, *p_lossPart;
static int *p_cand_i, *p_idx;
static bool s_init = false;

static inline void split_launch(const float* src, __half* h, __half* l, size_t n, float s)
{
    int n4 = (int)(n / 4);
    split4<<<(n4 + 255) / 256, 256>>>((const float4*)src, (__half2*)h, (__half2*)l, n4, s);
}

extern "C" void kernel_launch(void* const* d_in, const int* in_sizes, int n_in,
                              void* d_out, int out_size)
{
    if (!s_init) {
        GETSYM(p_bufB, g_bufB); GETSYM(p_bufC, g_bufC);
        GETSYM(p_bufD, g_bufD); GETSYM(p_bufZ, g_bufZ);
        GETSYM(p_zsth, g_zsth); GETSYM(p_zstl, g_zstl);
        GETSYM(p_g1h, g_g1h); GETSYM(p_g1l, g_g1l);
        GETSYM(p_g2h, g_g2h); GETSYM(p_g2l, g_g2l);
        GETSYM(p_g3h, g_g3h); GETSYM(p_g3l, g_g3l);
        GETSYM(p_v1h, g_v1h); GETSYM(p_v1l, g_v1l);
        GETSYM(p_v2h, g_v2h); GETSYM(p_v2l, g_v2l);
        GETSYM(p_v3h, g_v3h); GETSYM(p_v3l, g_v3l);
        GETSYM(p_v4h, g_v4h); GETSYM(p_v4l, g_v4l);
        GETSYM(p_znorm, g_znorm); GETSYM(p_enorm, g_enorm);
        GETSYM(p_cand_d, g_cand_d); GETSYM(p_cand_i, g_cand_i);
        GETSYM(p_idx, g_idx); GETSYM(p_lossPart, g_lossPart);
        cudaFuncSetAttribute(tc_gemm<1, 1, 0>,
                             cudaFuncAttributeMaxDynamicSharedMemorySize, GEMM_SMEM);
        cudaFuncSetAttribute(tc_gemm<0, 0, 1>,
                             cudaFuncAttributeMaxDynamicSharedMemorySize, GEMM_SMEM);
        s_init = true;
    }

    const float* x   = (const float*)d_in[0];
    const float* ew1 = (const float*)d_in[1];
    const float* eb1 = (const float*)d_in[2];
    const float* ew2 = (const float*)d_in[3];
    const float* eb2 = (const float*)d_in[4];
    const float* ew3 = (const float*)d_in[5];
    const float* eb3 = (const float*)d_in[6];
    const float* ew4 = (const float*)d_in[7];
    const float* eb4 = (const float*)d_in[8];
    const float* cb  = (const float*)d_in[9];
    const float* dw1 = (const float*)d_in[10];
    const float* db1 = (const float*)d_in[11];
    const float* dw2 = (const float*)d_in[12];
    const float* db2 = (const float*)d_in[13];
    const float* dw3 = (const float*)d_in[14];
    const float* db3 = (const float*)d_in[15];
    const float* dw4 = (const float*)d_in[16];
    const float* db4 = (const float*)d_in[17];
    float* out = (float*)d_out;

    dim3 blk(256);

    // ---- decoder weight splits (overlap with encoder via same stream order) ----
    split_launch(dw1, p_v1h, p_v1l, (size_t)1024 * 512, WSCALE);
    split_launch(dw2, p_v2h, p_v2l, (size_t)2048 * 1024, WSCALE);
    split_launch(dw3, p_v3h, p_v3l, (size_t)4096 * 2048, WSCALE);
    split_launch(dw4, p_v4h, p_v4l, (size_t)4096 * 4096, WSCALE);

    // ---- encoder (fp32, byte-identical to R3 passing run) ----
    sgemm_bias<true ><<<dim3(2048/128, BATCH/128), blk>>>(x,      ew1, eb1, p_bufB, BATCH, 2048, 4096);
    sgemm_bias<true ><<<dim3(1024/128, BATCH/128), blk>>>(p_bufB, ew2, eb2, p_bufC, BATCH, 1024, 2048);
    sgemm_bias<true ><<<dim3( 512/128, BATCH/128), blk>>>(p_bufC, ew3, eb3, p_bufD, BATCH,  512, 1024);
    sgemm_bias<false><<<dim3( 512/128, BATCH/128), blk>>>(p_bufD, ew4, eb4, p_bufZ, BATCH,  512,  512);

    // ---- VQ (fp32, R3-identical) ----
    rownorm512<<<(BATCH * 32 + 255) / 256, blk>>>(p_bufZ, p_znorm, BATCH);
    rownorm512<<<(NCODE * 32 + 255) / 256, blk>>>(cb, p_enorm, NCODE);
    vq_dist<<<dim3(NCODE / 128, BATCH / 128), blk>>>(p_bufZ, cb, p_znorm, p_enorm,
                                                     p_cand_d, p_cand_i);
    vq_argmin_final<<<BATCH / 256, blk>>>(p_cand_d, p_cand_i, p_idx, out + IDX_OFF);
    vq_gather<<<BATCH, 128>>>(p_bufZ, cb, p_idx, p_zsth, p_zstl, p_lossPart);
    loss_final<<<1, 256>>>(p_lossPart, out + LOSS_OFF);

    // ---- decoder (HMMA split-fp16, 3-product; pred_x rel_err ~1e-5) ----
    tc_gemm<1,1,0><<<dim3( 8, 64), 256, GEMM_SMEM>>>(p_zsth, p_zstl, p_v1h, p_v1l, db1,
                                                     p_g1h, p_g1l, nullptr, BATCH, 1024, 512);
    tc_gemm<1,1,0><<<dim3(16, 64), 256, GEMM_SMEM>>>(p_g1h, p_g1l, p_v2h, p_v2l, db2,
                                                     p_g2h, p_g2l, nullptr, BATCH, 2048, 1024);
    tc_gemm<1,1,0><<<dim3(32, 64), 256, GEMM_SMEM>>>(p_g2h, p_g2l, p_v3h, p_v3l, db3,
                                                     p_g3h, p_g3l, nullptr, BATCH, 4096, 2048);
    tc_gemm<0,0,1><<<dim3(32, 64), 256, GEMM_SMEM>>>(p_g3h, p_g3l, p_v4h, p_v4l, db4,
                                                     nullptr, nullptr, out, BATCH, 4096, 4096);
}